// round 1
// baseline (speedup 1.0000x reference)
#include <cuda_runtime.h>

#define DIMC   192
#define NH     6
#define HD     32
#define MLEN   256
#define NTOK   16384   // H*W = 128*128
#define BATCH  4
#define TILE   64
#define THREADS 256
#define QP     193     // padded row stride (odd -> conflict-free)
#define MP     257

// ---- scratch (device globals: no runtime allocation allowed) ----
__device__ float g_k[BATCH * MLEN * DIMC];
__device__ float g_v[BATCH * MLEN * DIMC];

// =====================================================================
// Kernel 1: pr = LN(prior); kv = pr @ Wkv; split into g_k / g_v
// grid = BATCH * 16 (16 rows per CTA), 256 threads
// =====================================================================
#define KV_ROWS 16
#define KV_KC   32
#define KV_SMEM_FLOATS (KV_ROWS*QP + KV_KC*384)

__global__ __launch_bounds__(THREADS) void kv_kernel(
    const float* __restrict__ prior,
    const float* __restrict__ g2, const float* __restrict__ b2,
    const float* __restrict__ Wkv)
{
    extern __shared__ float sm[];
    float* P  = sm;                 // [16][QP]
    float* Wc = sm + KV_ROWS*QP;    // [32][384]

    int b  = blockIdx.x >> 4;
    int m0 = (blockIdx.x & 15) * KV_ROWS;
    int tid = threadIdx.x;

    // load 16 rows of prior
    for (int idx = tid; idx < KV_ROWS*DIMC; idx += THREADS) {
        int r = idx / DIMC, k = idx % DIMC;
        P[r*QP + k] = prior[(size_t)(b*MLEN + m0 + r)*DIMC + k];
    }
    __syncthreads();

    // LN: 16 threads per row, 12 elems each
    {
        int row = tid >> 4, part = tid & 15;
        float s = 0.f, s2 = 0.f;
        for (int k = part*12; k < part*12 + 12; k++) {
            float v = P[row*QP + k]; s += v; s2 += v*v;
        }
        #pragma unroll
        for (int off = 8; off; off >>= 1) {
            s  += __shfl_xor_sync(0xffffffffu, s,  off);
            s2 += __shfl_xor_sync(0xffffffffu, s2, off);
        }
        float mu   = s * (1.f/DIMC);
        float rstd = rsqrtf(s2*(1.f/DIMC) - mu*mu + 1e-5f);
        for (int k = part*12; k < part*12 + 12; k++) {
            P[row*QP + k] = (P[row*QP + k] - mu) * rstd * g2[k] + b2[k];
        }
    }
    __syncthreads();

    // GEMM: [16 x 192] @ [192 x 384]
    int w = tid >> 5, lane = tid & 31;
    float acc[2][12];
    #pragma unroll
    for (int r = 0; r < 2; r++)
        #pragma unroll
        for (int j = 0; j < 12; j++) acc[r][j] = 0.f;

    for (int kc = 0; kc < DIMC/KV_KC; kc++) {
        for (int idx = tid; idx < KV_KC*384; idx += THREADS)
            Wc[idx] = Wkv[(size_t)kc*KV_KC*384 + idx];
        __syncthreads();
        for (int k = 0; k < KV_KC; k++) {
            float a0 = P[(w*2+0)*QP + kc*KV_KC + k];
            float a1 = P[(w*2+1)*QP + kc*KV_KC + k];
            #pragma unroll
            for (int jj = 0; jj < 12; jj++) {
                float wv = Wc[k*384 + lane + 32*jj];
                acc[0][jj] += a0 * wv;
                acc[1][jj] += a1 * wv;
            }
        }
        __syncthreads();
    }

    #pragma unroll
    for (int r = 0; r < 2; r++) {
        int m = m0 + w*2 + r;
        #pragma unroll
        for (int jj = 0; jj < 12; jj++) {
            int j = lane + 32*jj;
            float v = acc[r][jj];
            if (j < DIMC) g_k[(size_t)(b*MLEN + m)*DIMC + j]          = v;
            else          g_v[(size_t)(b*MLEN + m)*DIMC + (j - DIMC)] = v;
        }
    }
}

// =====================================================================
// Kernel 2: fused LN -> Q proj -> attention -> out proj -> residual
// grid = BATCH * (NTOK/TILE) = 1024, 256 threads
// smem: X[64][QP] | Q[64][QP] | S[64][256] (alias Wc[48][192]) | Kt[32][MP] V[256][32]
// =====================================================================
#define FUSED_SMEM_FLOATS (2*TILE*QP + TILE*MLEN + (HD*MP + MLEN*HD))

__global__ __launch_bounds__(THREADS) void fused_kernel(
    const float* __restrict__ x,
    const float* __restrict__ g1, const float* __restrict__ b1,
    const float* __restrict__ Wq, const float* __restrict__ Wp,
    const float* __restrict__ bp, float* __restrict__ out)
{
    extern __shared__ float sm[];
    float* X  = sm;                      // 64*QP ; later reused as O
    float* Q  = sm + TILE*QP;            // 64*QP ; later reused as R
    float* S  = Q  + TILE*QP;            // 64*256 scores
    float* Wc = S;                       // alias: weight chunk 48*192 (phases 2&4)
    float* Kt = S + TILE*MLEN;           // 32*MP (transposed K head)
    float* V  = Kt + HD*MP;              // 256*32

    int b  = blockIdx.x / (NTOK/TILE);
    int n0 = (blockIdx.x % (NTOK/TILE)) * TILE;
    int tid = threadIdx.x;
    int w = tid >> 5, lane = tid & 31;
    const size_t xbase = (size_t)b * DIMC * NTOK;

    // ---------- phase 1: transpose-load x tile + LayerNorm ----------
    for (int idx = tid; idx < TILE*DIMC; idx += THREADS) {
        int c = idx / TILE, i = idx % TILE;
        X[i*QP + c] = x[xbase + (size_t)c*NTOK + n0 + i];
    }
    __syncthreads();
    {
        int row = tid >> 2, part = tid & 3;  // 4 threads/token, 48 elems each
        float s = 0.f, s2 = 0.f;
        for (int k = part*48; k < part*48 + 48; k++) {
            float v = X[row*QP + k]; s += v; s2 += v*v;
        }
        s  += __shfl_xor_sync(0xffffffffu, s, 1);
        s  += __shfl_xor_sync(0xffffffffu, s, 2);
        s2 += __shfl_xor_sync(0xffffffffu, s2, 1);
        s2 += __shfl_xor_sync(0xffffffffu, s2, 2);
        float mu   = s * (1.f/DIMC);
        float rstd = rsqrtf(s2*(1.f/DIMC) - mu*mu + 1e-5f);
        for (int k = part*48; k < part*48 + 48; k++) {
            X[row*QP + k] = (X[row*QP + k] - mu) * rstd * g1[k] + b1[k];
        }
    }
    __syncthreads();

    // ---------- phase 2: Q = X @ Wq   (64x192 @ 192x192) ----------
    {
        float acc[8][6];
        #pragma unroll
        for (int ii = 0; ii < 8; ii++)
            #pragma unroll
            for (int jj = 0; jj < 6; jj++) acc[ii][jj] = 0.f;

        for (int kc = 0; kc < 4; kc++) {
            for (int idx = tid; idx < 48*DIMC; idx += THREADS)
                Wc[idx] = Wq[(size_t)kc*48*DIMC + idx];
            __syncthreads();
            for (int k = 0; k < 48; k++) {
                float wv[6];
                #pragma unroll
                for (int jj = 0; jj < 6; jj++) wv[jj] = Wc[k*DIMC + lane + 32*jj];
                #pragma unroll
                for (int ii = 0; ii < 8; ii++) {
                    float a = X[(w*8 + ii)*QP + kc*48 + k];
                    #pragma unroll
                    for (int jj = 0; jj < 6; jj++) acc[ii][jj] += a * wv[jj];
                }
            }
            __syncthreads();
        }
        #pragma unroll
        for (int ii = 0; ii < 8; ii++)
            #pragma unroll
            for (int jj = 0; jj < 6; jj++)
                Q[(w*8 + ii)*QP + lane + 32*jj] = acc[ii][jj];
    }
    __syncthreads();

    // ---------- phase 3: attention, per head ----------
    const float scale = 0.17677669529663687f;   // 32^-0.5
    for (int h = 0; h < NH; h++) {
        __syncthreads();  // prior head's PV done reading S/V
        for (int idx = tid; idx < MLEN*HD; idx += THREADS) {
            int m = idx >> 5, d = idx & 31;
            Kt[d*MP + m] = g_k[(size_t)(b*MLEN + m)*DIMC + h*HD + d];
            V[idx]       = g_v[(size_t)(b*MLEN + m)*DIMC + h*HD + d];
        }
        __syncthreads();

        // S = scale * Q_h @ Kt   (64 x 256)
        for (int mb = 0; mb < 4; mb++) {
            float acc[8][2];
            #pragma unroll
            for (int ii = 0; ii < 8; ii++) { acc[ii][0] = 0.f; acc[ii][1] = 0.f; }
            int m0a = mb*64 + lane, m1a = m0a + 32;
            for (int d = 0; d < HD; d++) {
                float k0 = Kt[d*MP + m0a];
                float k1 = Kt[d*MP + m1a];
                #pragma unroll
                for (int ii = 0; ii < 8; ii++) {
                    float qv = Q[(w*8 + ii)*QP + h*HD + d];
                    acc[ii][0] += qv * k0;
                    acc[ii][1] += qv * k1;
                }
            }
            #pragma unroll
            for (int ii = 0; ii < 8; ii++) {
                S[(w*8 + ii)*MLEN + m0a] = acc[ii][0] * scale;
                S[(w*8 + ii)*MLEN + m1a] = acc[ii][1] * scale;
            }
        }
        __syncthreads();

        // softmax over m (row = 256 values), one row per warp-iteration
        for (int rr = 0; rr < 8; rr++) {
            int row = w*8 + rr;
            float e[8], mx = -1e30f;
            #pragma unroll
            for (int j = 0; j < 8; j++) {
                e[j] = S[row*MLEN + lane + 32*j];
                mx = fmaxf(mx, e[j]);
            }
            #pragma unroll
            for (int off = 16; off; off >>= 1)
                mx = fmaxf(mx, __shfl_xor_sync(0xffffffffu, mx, off));
            float sum = 0.f;
            #pragma unroll
            for (int j = 0; j < 8; j++) { e[j] = __expf(e[j] - mx); sum += e[j]; }
            #pragma unroll
            for (int off = 16; off; off >>= 1)
                sum += __shfl_xor_sync(0xffffffffu, sum, off);
            float inv = 1.f / sum;
            #pragma unroll
            for (int j = 0; j < 8; j++)
                S[row*MLEN + lane + 32*j] = e[j] * inv;
        }
        __syncthreads();

        // O_h = P @ V_h  -> write into X columns [h*32, h*32+32)
        {
            float acc[8];
            #pragma unroll
            for (int ii = 0; ii < 8; ii++) acc[ii] = 0.f;
            for (int m = 0; m < MLEN; m++) {
                float vv = V[m*HD + lane];
                #pragma unroll
                for (int ii = 0; ii < 8; ii++)
                    acc[ii] += S[(w*8 + ii)*MLEN + m] * vv;
            }
            #pragma unroll
            for (int ii = 0; ii < 8; ii++)
                X[(w*8 + ii)*QP + h*HD + lane] = acc[ii];
        }
    }
    __syncthreads();

    // ---------- phase 4: R = O @ Wp + bp  (into Q buffer) ----------
    {
        float acc[8][6];
        #pragma unroll
        for (int ii = 0; ii < 8; ii++)
            #pragma unroll
            for (int jj = 0; jj < 6; jj++) acc[ii][jj] = 0.f;

        for (int kc = 0; kc < 4; kc++) {
            for (int idx = tid; idx < 48*DIMC; idx += THREADS)
                Wc[idx] = Wp[(size_t)kc*48*DIMC + idx];
            __syncthreads();
            for (int k = 0; k < 48; k++) {
                float wv[6];
                #pragma unroll
                for (int jj = 0; jj < 6; jj++) wv[jj] = Wc[k*DIMC + lane + 32*jj];
                #pragma unroll
                for (int ii = 0; ii < 8; ii++) {
                    float a = X[(w*8 + ii)*QP + kc*48 + k];
                    #pragma unroll
                    for (int jj = 0; jj < 6; jj++) acc[ii][jj] += a * wv[jj];
                }
            }
            __syncthreads();
        }
        #pragma unroll
        for (int ii = 0; ii < 8; ii++)
            #pragma unroll
            for (int jj = 0; jj < 6; jj++) {
                int j = lane + 32*jj;
                Q[(w*8 + ii)*QP + j] = acc[ii][jj] + bp[j];
            }
    }
    __syncthreads();

    // ---------- write out: transpose + residual (coalesced) ----------
    for (int idx = tid; idx < TILE*DIMC; idx += THREADS) {
        int c = idx / TILE, i = idx % TILE;
        size_t g = xbase + (size_t)c*NTOK + n0 + i;
        out[g] = Q[i*QP + c] + x[g];
    }
}

// =====================================================================
extern "C" void kernel_launch(void* const* d_in, const int* in_sizes, int n_in,
                              void* d_out, int out_size)
{
    (void)in_sizes; (void)n_in; (void)out_size;
    const float* x     = (const float*)d_in[0];
    const float* prior = (const float*)d_in[1];
    const float* ln1_g = (const float*)d_in[2];
    const float* ln1_b = (const float*)d_in[3];
    const float* ln2_g = (const float*)d_in[4];
    const float* ln2_b = (const float*)d_in[5];
    const float* Wq    = (const float*)d_in[6];
    const float* Wkv   = (const float*)d_in[7];
    const float* Wp    = (const float*)d_in[8];
    const float* bp    = (const float*)d_in[9];
    float* out = (float*)d_out;

    const int kv_smem    = KV_SMEM_FLOATS    * (int)sizeof(float);   //  ~62 KB
    const int fused_smem = FUSED_SMEM_FLOATS * (int)sizeof(float);   // ~225 KB

    cudaFuncSetAttribute(kv_kernel,    cudaFuncAttributeMaxDynamicSharedMemorySize, kv_smem);
    cudaFuncSetAttribute(fused_kernel, cudaFuncAttributeMaxDynamicSharedMemorySize, fused_smem);

    kv_kernel<<<BATCH * (MLEN/KV_ROWS), THREADS, kv_smem>>>(prior, ln2_g, ln2_b, Wkv);
    fused_kernel<<<BATCH * (NTOK/TILE), THREADS, fused_smem>>>(
        x, ln1_g, ln1_b, Wq, Wp, bp, out);
}